// round 16
// baseline (speedup 1.0000x reference)
#include <cuda_runtime.h>
#include <cuda_fp16.h>
#include <cstdint>
#include <cstddef>

// Problem constants
#define BB   32
#define CC   256
#define HH   56
#define WW   56
#define HWSZ 3136          // 56*56
#define GG   4
#define KS   7
#define KK2  49            // 7*7
#define CRR  64            // C / 4
#define NTOT (BB * HWSZ)   // 100352 = 784 * 128

typedef unsigned long long ull;

// Scratch (device globals: allocation-free per harness rules)
__device__ __half g_sc[(size_t)BB * CC * HWSZ];   // gelu(dw) fp16 (single)
__device__ float g_pooled[BB * CC];
__device__ float g_wk[(size_t)BB * CC * KK2];     // per-(b,c) 7x7 kernels
__device__ __half g_wb_hi[CC * CC];               // pw_w fp16 hi
__device__ __half g_wb_lo[CC * CC];               // pw_w fp16 lo (residual)

// ---------------------------------------------------------------------------
// generic helpers
// ---------------------------------------------------------------------------
__device__ __forceinline__ float gelu_f(float x) {
    return 0.5f * x * (1.0f + erff(x * 0.70710678118654752440f));
}
__device__ __forceinline__ ull pack2(float lo, float hi) {
    ull r; asm("mov.b64 %0, {%1, %2};" : "=l"(r) : "f"(lo), "f"(hi)); return r;
}
__device__ __forceinline__ void fma2(ull& d, ull a, ull b) {
    asm("fma.rn.f32x2 %0, %1, %2, %0;" : "+l"(d) : "l"(a), "l"(b));
}
__device__ __forceinline__ float2 unpack2(ull v) {
    float2 r; asm("mov.b64 {%0, %1}, %2;" : "=f"(r.x), "=f"(r.y) : "l"(v)); return r;
}
__device__ __forceinline__ float4 ldcs4(const float* p) {
    float4 v;
    asm("ld.global.cs.v4.f32 {%0,%1,%2,%3}, [%4];"
        : "=f"(v.x), "=f"(v.y), "=f"(v.z), "=f"(v.w) : "l"(p));
    return v;
}
__device__ __forceinline__ void stcs2(float* p, float2 v) {
    asm("st.global.cs.v2.f32 [%0], {%1,%2};" :: "l"(p), "f"(v.x), "f"(v.y));
}
__device__ __forceinline__ uint32_t pk_h2(float a, float b) {
    const __half2 v = __floats2half2_rn(a, b);
    return *reinterpret_cast<const uint32_t*>(&v);
}
__device__ __forceinline__ uint32_t smem_u32(const void* p) {
    uint32_t a;
    asm("{ .reg .u64 t; cvta.to.shared.u64 t, %1; cvt.u32.u64 %0, t; }"
        : "=r"(a) : "l"(p));
    return a;
}
__device__ __forceinline__ void cpa16(uint32_t dst, const void* src) {
    asm volatile("cp.async.cg.shared.global [%0], [%1], 16;" :: "r"(dst), "l"(src));
}
#define CPA_COMMIT() asm volatile("cp.async.commit_group;" ::: "memory")
#define CPA_WAIT0()  asm volatile("cp.async.wait_group 0;" ::: "memory")
#define CPA_WAIT1()  asm volatile("cp.async.wait_group 1;" ::: "memory")

// HMMA m16n8k16 fp16 (row.col), fp32 accumulate — portable sm_80+ path
__device__ __forceinline__ void hmma(float* c, const uint32_t* a, const uint32_t* b) {
    asm volatile(
        "mma.sync.aligned.m16n8k16.row.col.f32.f16.f16.f32 "
        "{%0,%1,%2,%3}, {%4,%5,%6,%7}, {%8,%9}, {%0,%1,%2,%3};"
        : "+f"(c[0]), "+f"(c[1]), "+f"(c[2]), "+f"(c[3])
        : "r"(a[0]), "r"(a[1]), "r"(a[2]), "r"(a[3]), "r"(b[0]), "r"(b[1]));
}
__device__ __forceinline__ void ldsm4(uint32_t* r, uint32_t addr) {
    asm volatile("ldmatrix.sync.aligned.m8n8.x4.shared.b16 {%0,%1,%2,%3}, [%4];"
                 : "=r"(r[0]), "=r"(r[1]), "=r"(r[2]), "=r"(r[3]) : "r"(addr));
}
__device__ __forceinline__ void ldsm4t(uint32_t* r, uint32_t addr) {
    asm volatile("ldmatrix.sync.aligned.m8n8.x4.trans.shared.b16 {%0,%1,%2,%3}, [%4];"
                 : "=r"(r[0]), "=r"(r[1]), "=r"(r[2]), "=r"(r[3]) : "r"(addr));
}

// ---------------------------------------------------------------------------
// Kernel 1: pooled[b,c] = mean over H,W of r
// ---------------------------------------------------------------------------
__global__ void pool_kernel(const float* __restrict__ r) {
    const int bc = blockIdx.x;
    const float* p = r + (size_t)bc * HWSZ;
    float s = 0.f;
    #pragma unroll 4
    for (int i = threadIdx.x; i < HWSZ / 4; i += 256) {
        float4 v = ldcs4(p + i * 4);
        s += (v.x + v.y) + (v.z + v.w);
    }
    __shared__ float red[8];
    #pragma unroll
    for (int o = 16; o > 0; o >>= 1) s += __shfl_down_sync(0xFFFFFFFFu, s, o);
    if ((threadIdx.x & 31) == 0) red[threadIdx.x >> 5] = s;
    __syncthreads();
    if (threadIdx.x < 8) {
        s = red[threadIdx.x];
        #pragma unroll
        for (int o = 4; o > 0; o >>= 1) s += __shfl_down_sync(0xFFu, s, o);
        if (threadIdx.x == 0) g_pooled[bc] = s * (1.0f / (float)HWSZ);
    }
}

// ---------------------------------------------------------------------------
// Kernel 2: SE weight generation -> g_wk[b,c,49]
// ---------------------------------------------------------------------------
__global__ void wgen_kernel(const float* __restrict__ w1, const float* __restrict__ b1,
                            const float* __restrict__ w2, const float* __restrict__ b2,
                            const float* __restrict__ weight, const float* __restrict__ bscale) {
    const int b = blockIdx.x;
    const int t = threadIdx.x;
    __shared__ float ps[CC];
    __shared__ float hs[CRR];

    ps[t] = g_pooled[b * CC + t];
    __syncthreads();

    if (t < CRR) {
        float acc = b1[t];
        const float* wr = w1 + (size_t)t * CC;
        #pragma unroll 4
        for (int c = 0; c < CC; c++) acc = fmaf(ps[c], wr[c], acc);
        hs[t] = gelu_f(acc);
    }
    __syncthreads();

    float vals[GG][2];
    #pragma unroll
    for (int g = 0; g < GG; g++) {
        #pragma unroll
        for (int e = 0; e < 2; e++) {
            const int row = (g * CC + t) * 2 + e;
            float acc = b2[row];
            const float* wr = w2 + (size_t)row * CRR;
            #pragma unroll 4
            for (int k = 0; k < CRR; k++) acc = fmaf(hs[k], wr[k], acc);
            vals[g][e] = acc;
        }
    }

    float m = fmaxf(fmaxf(vals[0][0], vals[1][0]), fmaxf(vals[2][0], vals[3][0]));
    float alpha[GG];
    float ssum = 0.f;
    #pragma unroll
    for (int g = 0; g < GG; g++) { alpha[g] = expf(vals[g][0] - m); ssum += alpha[g]; }
    const float inv = 1.0f / ssum;
    float betasum = 0.f;
    #pragma unroll
    for (int g = 0; g < GG; g++) {
        alpha[g] *= inv;
        betasum += tanhf(vals[g][1] * expf(bscale[g * CC + t]) * 0.1f);
    }

    float* out = g_wk + ((size_t)b * CC + t) * KK2;
    #pragma unroll
    for (int k = 0; k < KK2; k++) {
        float acc = betasum;
        #pragma unroll
        for (int g = 0; g < GG; g++)
            acc = fmaf(alpha[g], weight[((size_t)g * CC + t) * KK2 + k], acc);
        out[k] = acc;
    }
}

// ---------------------------------------------------------------------------
// Kernel 2b: preconvert pw_w -> fp16 hi + fp16 residual lo
// ---------------------------------------------------------------------------
__global__ void wconv_kernel(const float* __restrict__ w) {
    const int i = blockIdx.x * 256 + threadIdx.x;
    const float x = w[i];
    const __half h = __float2half_rn(x);
    g_wb_hi[i] = h;
    g_wb_lo[i] = __float2half_rn(x - __half2float(h));
}

// ---------------------------------------------------------------------------
// Kernel 3: dynamic depthwise 7x7 conv (pad 3) + exact GELU -> fp16 (single)
// ONE plane per 224-thread block (grid 8192). Per-thread tile 4x4.
// launch_bounds(224,4).
// ---------------------------------------------------------------------------
__global__ void __launch_bounds__(224, 4) dw_kernel(const float* __restrict__ s) {
    const int bc = blockIdx.x;
    __shared__ __align__(16) float sm[62 * 64];
    __shared__ ull wsm[KK2];
    const int t = threadIdx.x;

    {
        float4* z = reinterpret_cast<float4*>(sm);
        const float4 zv = make_float4(0.f, 0.f, 0.f, 0.f);
        for (int i = t; i < 62 * 64 / 4; i += 224) z[i] = zv;
    }
    if (t < KK2) {
        const float w = g_wk[(size_t)bc * KK2 + t];
        wsm[t] = pack2(w, w);
    }
    __syncthreads();

    for (int i = t; i < 784; i += 224) {
        const int y = i / 14;
        const int x4 = i - y * 14;
        const float4 v = ldcs4(s + (size_t)bc * HWSZ + y * WW + x4 * 4);
        float* dst = &sm[(y + 3) * 64 + 3 + x4 * 4];
        dst[0] = v.x; dst[1] = v.y; dst[2] = v.z; dst[3] = v.w;
    }
    __syncthreads();

    if (t >= 196) return;
    const int ytile = t / 14;
    const int xtile = t - ytile * 14;
    const int y0 = ytile * 4;
    const int x0 = xtile * 4;
    const size_t obase = (size_t)bc * HWSZ;

    ull acc[4][2];
    #pragma unroll
    for (int oy = 0; oy < 4; oy++) { acc[oy][0] = 0ull; acc[oy][1] = 0ull; }

    #pragma unroll
    for (int r = 0; r < 10; r++) {
        const float* row = &sm[(y0 + r) * 64 + x0];
        const float4 q0 = *reinterpret_cast<const float4*>(row);
        const float4 q1 = *reinterpret_cast<const float4*>(row + 4);
        const float4 q2 = *reinterpret_cast<const float4*>(row + 8);
        const float f[12] = {q0.x, q0.y, q0.z, q0.w, q1.x, q1.y, q1.z, q1.w,
                             q2.x, q2.y, q2.z, q2.w};
        ull p[9];
        #pragma unroll
        for (int i = 0; i < 9; i++) p[i] = pack2(f[i], f[i + 1]);

        #pragma unroll
        for (int oy = 0; oy < 4; oy++) {
            const int ky = r - oy;
            if (ky >= 0 && ky < 7) {
                #pragma unroll
                for (int kx = 0; kx < 7; kx++) {
                    const ull w = wsm[ky * 7 + kx];
                    fma2(acc[oy][0], w, p[kx]);
                    fma2(acc[oy][1], w, p[kx + 2]);
                }
            }
        }
    }

    #pragma unroll
    for (int oy = 0; oy < 4; oy++) {
        const float2 v0 = unpack2(acc[oy][0]);
        const float2 v1 = unpack2(acc[oy][1]);
        const uint32_t h01 = pk_h2(gelu_f(v0.x), gelu_f(v0.y));
        const uint32_t h23 = pk_h2(gelu_f(v1.x), gelu_f(v1.y));
        const size_t off = obase + (y0 + oy) * WW + x0;   // 4-aligned -> 8B OK
        *reinterpret_cast<uint2*>(g_sc + off) = make_uint2(h01, h23);
    }
}

// ---------------------------------------------------------------------------
// Kernel 4: pointwise conv on tensor cores (mma.sync fp16, A=hi+lo, B=fp16)
// D = (Ah + Al) * Bh  -> 2 HMMA per k-step (was 3).
// 3-stage cp.async ring, one sync per chunk, K-chunk 16. Tile 128x128,
// warp tile 64x32, 2 blocks/SM. Stage = A(hi+lo) 8KB + B 4KB; 3 stages=36KB.
// XOR swizzles as before (conflict-free LDSM).
// ---------------------------------------------------------------------------
#define A_MAT_BYTES 4096                  // 128 rows x 32 B
#define B_MAT_BYTES 4096                  // 16 rows x 256 B
#define A_STAGE_BYTES (2 * A_MAT_BYTES)   // hi+lo
#define B_STAGE_BYTES (B_MAT_BYTES)

__global__ void __launch_bounds__(256, 2) pw_mma_kernel(const float* __restrict__ bias,
                                                        float* __restrict__ out) {
    __shared__ __align__(16) __half sA[3][2][A_MAT_BYTES / 2];  // 24 KB
    __shared__ __align__(16) __half sB[3][B_MAT_BYTES / 2];     // 12 KB

    const int t = threadIdx.x;
    const int lane = t & 31;
    const int wid = t >> 5;
    const int n0 = blockIdx.x * 128;
    const int dBase = blockIdx.y * 128;

    const int m_warp = (wid >> 2) * 64;   // 0 or 64
    const int n_warp = (wid & 3) * 32;    // 0..96

    const uint32_t baseA = smem_u32(sA);
    const uint32_t baseB = smem_u32(sB);

    // ---- cp.async destinations (swizzled) ----
    const int a_row = t >> 1;             // 0..127
    const int a_half = t & 1;             // 0/1
    const size_t a_g = (size_t)(dBase + a_row) * CC + a_half * 8;
    const uint32_t a_off = (uint32_t)(a_row * 32 + ((a_half ^ ((a_row >> 2) & 1)) << 4));

    const int b_row = t >> 4;             // 0..15 (k)
    const int b_seg = t & 15;             // 16B chunk (8 n)
    const int n_t = n0 + b_seg * 8;       // 8 | 3136 -> single batch per seg
    const int b_bt = n_t / HWSZ;
    const size_t b_g = ((size_t)b_bt * CC + b_row) * HWSZ + (n_t - b_bt * HWSZ);
    const uint32_t b_off = (uint32_t)(b_row * 256 + ((b_seg ^ (b_row & 7)) << 4));

    // ---- LDSM source offsets (swizzled, stage-invariant) ----
    uint32_t aA_off[4];
    #pragma unroll
    for (int mf = 0; mf < 4; mf++) {
        const int row = m_warp + mf * 16 + (lane & 7) + ((lane >> 3) & 1) * 8;
        const int half = lane >> 4;
        aA_off[mf] = (uint32_t)(row * 32 + ((half ^ ((row >> 2) & 1)) << 4));
    }
    const int b_krow = ((lane >> 3) & 1) * 8 + (lane & 7);
    uint32_t aB_off[2];
    #pragma unroll
    for (int nfp = 0; nfp < 2; nfp++) {
        const int chunk = (n_warp >> 3) + (lane >> 4) + nfp * 2;
        aB_off[nfp] = (uint32_t)(b_krow * 256 + ((chunk ^ (b_krow & 7)) << 4));
    }

    float acc[4][4][4];
    #pragma unroll
    for (int i = 0; i < 4; i++)
        #pragma unroll
        for (int j = 0; j < 4; j++)
            #pragma unroll
            for (int q = 0; q < 4; q++) acc[i][j][q] = 0.f;

    auto load_chunk = [&](int ch, int buf) {
        const int c0 = ch * 16;
        const uint32_t sa = baseA + (uint32_t)buf * A_STAGE_BYTES;
        const uint32_t sb = baseB + (uint32_t)buf * B_STAGE_BYTES;
        cpa16(sa + a_off, g_wb_hi + a_g + c0);
        cpa16(sa + A_MAT_BYTES + a_off, g_wb_lo + a_g + c0);
        cpa16(sb + b_off, g_sc + b_g + (size_t)c0 * HWSZ);
        CPA_COMMIT();
    };

    load_chunk(0, 0);
    load_chunk(1, 1);

    int buf = 0;
    for (int ch = 0; ch < 16; ch++) {
        CPA_WAIT1();
        __syncthreads();

        const uint32_t sa = baseA + (uint32_t)buf * A_STAGE_BYTES;
        const uint32_t sb = baseB + (uint32_t)buf * B_STAGE_BYTES;

        uint32_t bh[4][2];
        #pragma unroll
        for (int nfp = 0; nfp < 2; nfp++) {
            uint32_t r[4];
            ldsm4t(r, sb + aB_off[nfp]);
            bh[nfp * 2 + 0][0] = r[0]; bh[nfp * 2 + 0][1] = r[1];
            bh[nfp * 2 + 1][0] = r[2]; bh[nfp * 2 + 1][1] = r[3];
        }
        #pragma unroll
        for (int mf = 0; mf < 4; mf++) {
            uint32_t ah[4], al[4];
            ldsm4(ah, sa + aA_off[mf]);
            ldsm4(al, sa + A_MAT_BYTES + aA_off[mf]);
            #pragma unroll
            for (int nf = 0; nf < 4; nf++) {
                hmma(acc[mf][nf], ah, bh[nf]);
                hmma(acc[mf][nf], al, bh[nf]);
            }
        }

        const int nxt = ch + 2;
        if (nxt < 16) {
            int nbuf = buf - 1;
            if (nbuf < 0) nbuf = 2;      // (ch+2)%3 given buf=(ch)%3
            load_chunk(nxt, nbuf);
        } else {
            CPA_COMMIT();                 // keep group counting consistent
        }
        buf++;
        if (buf == 3) buf = 0;
    }

    // ---- epilogue (bias via __ldg) ----
    const int g = lane >> 2;
    const int tig = lane & 3;
    #pragma unroll
    for (int mf = 0; mf < 4; mf++) {
        const int d0 = dBase + m_warp + mf * 16 + g;
        const float bb0 = __ldg(bias + d0);
        const float bb1 = __ldg(bias + d0 + 8);
        #pragma unroll
        for (int nf = 0; nf < 4; nf++) {
            const int nt = n0 + n_warp + nf * 8 + tig * 2;
            const int bt = nt / HWSZ;
            const int pp = nt - bt * HWSZ;
            float2 v0, v1;
            v0.x = acc[mf][nf][0] + bb0;
            v0.y = acc[mf][nf][1] + bb0;
            v1.x = acc[mf][nf][2] + bb1;
            v1.y = acc[mf][nf][3] + bb1;
            stcs2(out + ((size_t)bt * CC + d0) * HWSZ + pp, v0);
            stcs2(out + ((size_t)bt * CC + d0 + 8) * HWSZ + pp, v1);
        }
    }
}

// ---------------------------------------------------------------------------
// launch
// ---------------------------------------------------------------------------
extern "C" void kernel_launch(void* const* d_in, const int* in_sizes, int n_in,
                              void* d_out, int out_size) {
    (void)in_sizes; (void)n_in; (void)out_size;
    const float* s      = (const float*)d_in[0];
    const float* r      = (const float*)d_in[1];
    const float* pw1    = (const float*)d_in[2];
    const float* pb1    = (const float*)d_in[3];
    const float* pw2    = (const float*)d_in[4];
    const float* pb2    = (const float*)d_in[5];
    const float* weight = (const float*)d_in[6];
    const float* bscale = (const float*)d_in[7];
    const float* pww    = (const float*)d_in[8];
    const float* pwb    = (const float*)d_in[9];
    float* out = (float*)d_out;

    pool_kernel<<<BB * CC, 256>>>(r);
    wgen_kernel<<<BB, 256>>>(pw1, pb1, pw2, pb2, weight, bscale);
    wconv_kernel<<<CC * CC / 256, 256>>>(pww);
    dw_kernel<<<BB * CC, 224>>>(s);
    dim3 grid(NTOT / 128, CC / 128, 1);
    pw_mma_kernel<<<grid, 256>>>(pwb, out);
}

// round 17
// speedup vs baseline: 1.5267x; 1.5267x over previous
#include <cuda_runtime.h>
#include <cuda_fp16.h>
#include <cstdint>
#include <cstddef>

// Problem constants
#define BB   32
#define CC   256
#define HH   56
#define WW   56
#define HWSZ 3136          // 56*56
#define GG   4
#define KS   7
#define KK2  49            // 7*7
#define CRR  64            // C / 4
#define NTOT (BB * HWSZ)   // 100352 = 784 * 128

typedef unsigned long long ull;

// Scratch (device globals: allocation-free per harness rules)
__device__ __half g_sc[(size_t)BB * CC * HWSZ];   // gelu(dw) fp16 (single)
__device__ float g_pooled[BB * CC];
__device__ float g_wk[(size_t)BB * CC * KK2];     // per-(b,c) 7x7 kernels
__device__ __half g_wb_hi[CC * CC];               // pw_w fp16 hi
__device__ __half g_wb_lo[CC * CC];               // pw_w fp16 lo (residual)

// ---------------------------------------------------------------------------
// generic helpers
// ---------------------------------------------------------------------------
__device__ __forceinline__ float gelu_f(float x) {
    return 0.5f * x * (1.0f + erff(x * 0.70710678118654752440f));
}
__device__ __forceinline__ ull pack2(float lo, float hi) {
    ull r; asm("mov.b64 %0, {%1, %2};" : "=l"(r) : "f"(lo), "f"(hi)); return r;
}
__device__ __forceinline__ void fma2(ull& d, ull a, ull b) {
    asm("fma.rn.f32x2 %0, %1, %2, %0;" : "+l"(d) : "l"(a), "l"(b));
}
__device__ __forceinline__ float2 unpack2(ull v) {
    float2 r; asm("mov.b64 {%0, %1}, %2;" : "=f"(r.x), "=f"(r.y) : "l"(v)); return r;
}
__device__ __forceinline__ float4 ldcs4(const float* p) {
    float4 v;
    asm("ld.global.cs.v4.f32 {%0,%1,%2,%3}, [%4];"
        : "=f"(v.x), "=f"(v.y), "=f"(v.z), "=f"(v.w) : "l"(p));
    return v;
}
__device__ __forceinline__ void stcs2(float* p, float2 v) {
    asm("st.global.cs.v2.f32 [%0], {%1,%2};" :: "l"(p), "f"(v.x), "f"(v.y));
}
__device__ __forceinline__ uint32_t pk_h2(float a, float b) {
    const __half2 v = __floats2half2_rn(a, b);
    return *reinterpret_cast<const uint32_t*>(&v);
}
__device__ __forceinline__ uint32_t smem_u32(const void* p) {
    uint32_t a;
    asm("{ .reg .u64 t; cvta.to.shared.u64 t, %1; cvt.u32.u64 %0, t; }"
        : "=r"(a) : "l"(p));
    return a;
}
__device__ __forceinline__ void cpa16(uint32_t dst, const void* src) {
    asm volatile("cp.async.cg.shared.global [%0], [%1], 16;" :: "r"(dst), "l"(src));
}
#define CPA_COMMIT() asm volatile("cp.async.commit_group;" ::: "memory")
#define CPA_WAIT0()  asm volatile("cp.async.wait_group 0;" ::: "memory")
#define CPA_WAIT1()  asm volatile("cp.async.wait_group 1;" ::: "memory")

// HMMA m16n8k16 fp16 (row.col), fp32 accumulate — portable sm_80+ path
__device__ __forceinline__ void hmma(float* c, const uint32_t* a, const uint32_t* b) {
    asm volatile(
        "mma.sync.aligned.m16n8k16.row.col.f32.f16.f16.f32 "
        "{%0,%1,%2,%3}, {%4,%5,%6,%7}, {%8,%9}, {%0,%1,%2,%3};"
        : "+f"(c[0]), "+f"(c[1]), "+f"(c[2]), "+f"(c[3])
        : "r"(a[0]), "r"(a[1]), "r"(a[2]), "r"(a[3]), "r"(b[0]), "r"(b[1]));
}
__device__ __forceinline__ void ldsm4(uint32_t* r, uint32_t addr) {
    asm volatile("ldmatrix.sync.aligned.m8n8.x4.shared.b16 {%0,%1,%2,%3}, [%4];"
                 : "=r"(r[0]), "=r"(r[1]), "=r"(r[2]), "=r"(r[3]) : "r"(addr));
}
__device__ __forceinline__ void ldsm4t(uint32_t* r, uint32_t addr) {
    asm volatile("ldmatrix.sync.aligned.m8n8.x4.trans.shared.b16 {%0,%1,%2,%3}, [%4];"
                 : "=r"(r[0]), "=r"(r[1]), "=r"(r[2]), "=r"(r[3]) : "r"(addr));
}

// ---------------------------------------------------------------------------
// Kernel 1: pooled[b,c] = mean over H,W of r
// ---------------------------------------------------------------------------
__global__ void pool_kernel(const float* __restrict__ r) {
    const int bc = blockIdx.x;
    const float* p = r + (size_t)bc * HWSZ;
    float s = 0.f;
    #pragma unroll 4
    for (int i = threadIdx.x; i < HWSZ / 4; i += 256) {
        float4 v = ldcs4(p + i * 4);
        s += (v.x + v.y) + (v.z + v.w);
    }
    __shared__ float red[8];
    #pragma unroll
    for (int o = 16; o > 0; o >>= 1) s += __shfl_down_sync(0xFFFFFFFFu, s, o);
    if ((threadIdx.x & 31) == 0) red[threadIdx.x >> 5] = s;
    __syncthreads();
    if (threadIdx.x < 8) {
        s = red[threadIdx.x];
        #pragma unroll
        for (int o = 4; o > 0; o >>= 1) s += __shfl_down_sync(0xFFu, s, o);
        if (threadIdx.x == 0) g_pooled[bc] = s * (1.0f / (float)HWSZ);
    }
}

// ---------------------------------------------------------------------------
// Kernel 2: SE weight generation -> g_wk[b,c,49]
// ---------------------------------------------------------------------------
__global__ void wgen_kernel(const float* __restrict__ w1, const float* __restrict__ b1,
                            const float* __restrict__ w2, const float* __restrict__ b2,
                            const float* __restrict__ weight, const float* __restrict__ bscale) {
    const int b = blockIdx.x;
    const int t = threadIdx.x;
    __shared__ float ps[CC];
    __shared__ float hs[CRR];

    ps[t] = g_pooled[b * CC + t];
    __syncthreads();

    if (t < CRR) {
        float acc = b1[t];
        const float* wr = w1 + (size_t)t * CC;
        #pragma unroll 4
        for (int c = 0; c < CC; c++) acc = fmaf(ps[c], wr[c], acc);
        hs[t] = gelu_f(acc);
    }
    __syncthreads();

    float vals[GG][2];
    #pragma unroll
    for (int g = 0; g < GG; g++) {
        #pragma unroll
        for (int e = 0; e < 2; e++) {
            const int row = (g * CC + t) * 2 + e;
            float acc = b2[row];
            const float* wr = w2 + (size_t)row * CRR;
            #pragma unroll 4
            for (int k = 0; k < CRR; k++) acc = fmaf(hs[k], wr[k], acc);
            vals[g][e] = acc;
        }
    }

    float m = fmaxf(fmaxf(vals[0][0], vals[1][0]), fmaxf(vals[2][0], vals[3][0]));
    float alpha[GG];
    float ssum = 0.f;
    #pragma unroll
    for (int g = 0; g < GG; g++) { alpha[g] = expf(vals[g][0] - m); ssum += alpha[g]; }
    const float inv = 1.0f / ssum;
    float betasum = 0.f;
    #pragma unroll
    for (int g = 0; g < GG; g++) {
        alpha[g] *= inv;
        betasum += tanhf(vals[g][1] * expf(bscale[g * CC + t]) * 0.1f);
    }

    float* out = g_wk + ((size_t)b * CC + t) * KK2;
    #pragma unroll
    for (int k = 0; k < KK2; k++) {
        float acc = betasum;
        #pragma unroll
        for (int g = 0; g < GG; g++)
            acc = fmaf(alpha[g], weight[((size_t)g * CC + t) * KK2 + k], acc);
        out[k] = acc;
    }
}

// ---------------------------------------------------------------------------
// Kernel 2b: preconvert pw_w -> fp16 hi + fp16 residual lo
// ---------------------------------------------------------------------------
__global__ void wconv_kernel(const float* __restrict__ w) {
    const int i = blockIdx.x * 256 + threadIdx.x;
    const float x = w[i];
    const __half h = __float2half_rn(x);
    g_wb_hi[i] = h;
    g_wb_lo[i] = __float2half_rn(x - __half2float(h));
}

// ---------------------------------------------------------------------------
// Kernel 3: dynamic depthwise 7x7 conv (pad 3) + exact GELU -> fp16 (single)
// ONE plane per 224-thread block (grid 8192). Per-thread tile 4x4.
// launch_bounds(224,4).
// ---------------------------------------------------------------------------
__global__ void __launch_bounds__(224, 4) dw_kernel(const float* __restrict__ s) {
    const int bc = blockIdx.x;
    __shared__ __align__(16) float sm[62 * 64];
    __shared__ ull wsm[KK2];
    const int t = threadIdx.x;

    {
        float4* z = reinterpret_cast<float4*>(sm);
        const float4 zv = make_float4(0.f, 0.f, 0.f, 0.f);
        for (int i = t; i < 62 * 64 / 4; i += 224) z[i] = zv;
    }
    if (t < KK2) {
        const float w = g_wk[(size_t)bc * KK2 + t];
        wsm[t] = pack2(w, w);
    }
    __syncthreads();

    for (int i = t; i < 784; i += 224) {
        const int y = i / 14;
        const int x4 = i - y * 14;
        const float4 v = ldcs4(s + (size_t)bc * HWSZ + y * WW + x4 * 4);
        float* dst = &sm[(y + 3) * 64 + 3 + x4 * 4];
        dst[0] = v.x; dst[1] = v.y; dst[2] = v.z; dst[3] = v.w;
    }
    __syncthreads();

    if (t >= 196) return;
    const int ytile = t / 14;
    const int xtile = t - ytile * 14;
    const int y0 = ytile * 4;
    const int x0 = xtile * 4;
    const size_t obase = (size_t)bc * HWSZ;

    ull acc[4][2];
    #pragma unroll
    for (int oy = 0; oy < 4; oy++) { acc[oy][0] = 0ull; acc[oy][1] = 0ull; }

    #pragma unroll
    for (int r = 0; r < 10; r++) {
        const float* row = &sm[(y0 + r) * 64 + x0];
        const float4 q0 = *reinterpret_cast<const float4*>(row);
        const float4 q1 = *reinterpret_cast<const float4*>(row + 4);
        const float4 q2 = *reinterpret_cast<const float4*>(row + 8);
        const float f[12] = {q0.x, q0.y, q0.z, q0.w, q1.x, q1.y, q1.z, q1.w,
                             q2.x, q2.y, q2.z, q2.w};
        ull p[9];
        #pragma unroll
        for (int i = 0; i < 9; i++) p[i] = pack2(f[i], f[i + 1]);

        #pragma unroll
        for (int oy = 0; oy < 4; oy++) {
            const int ky = r - oy;
            if (ky >= 0 && ky < 7) {
                #pragma unroll
                for (int kx = 0; kx < 7; kx++) {
                    const ull w = wsm[ky * 7 + kx];
                    fma2(acc[oy][0], w, p[kx]);
                    fma2(acc[oy][1], w, p[kx + 2]);
                }
            }
        }
    }

    #pragma unroll
    for (int oy = 0; oy < 4; oy++) {
        const float2 v0 = unpack2(acc[oy][0]);
        const float2 v1 = unpack2(acc[oy][1]);
        const uint32_t h01 = pk_h2(gelu_f(v0.x), gelu_f(v0.y));
        const uint32_t h23 = pk_h2(gelu_f(v1.x), gelu_f(v1.y));
        const size_t off = obase + (y0 + oy) * WW + x0;   // 4-aligned -> 8B OK
        *reinterpret_cast<uint2*>(g_sc + off) = make_uint2(h01, h23);
    }
}

// ---------------------------------------------------------------------------
// Kernel 4: pointwise conv on tensor cores (mma.sync fp16, A=hi+lo, B=fp16)
// D = (Ah + Al) * Bh  -> 2 HMMA per k-step (was 3).
// 3-stage cp.async ring, one sync per chunk, K-chunk 16. Tile 128x128,
// warp tile 64x32, 2 blocks/SM. Stage = A(hi+lo) 8KB + B 4KB; 3 stages=36KB.
// XOR swizzles as before (conflict-free LDSM).
// ---------------------------------------------------------------------------
#define A_MAT_BYTES 4096                  // 128 rows x 32 B
#define B_MAT_BYTES 4096                  // 16 rows x 256 B
#define A_STAGE_BYTES (2 * A_MAT_BYTES)   // hi+lo
#define B_STAGE_BYTES (B_MAT_BYTES)

__global__ void __launch_bounds__(256, 2) pw_mma_kernel(const float* __restrict__ bias,
                                                        float* __restrict__ out) {
    __shared__ __align__(16) __half sA[3][2][A_MAT_BYTES / 2];  // 24 KB
    __shared__ __align__(16) __half sB[3][B_MAT_BYTES / 2];     // 12 KB

    const int t = threadIdx.x;
    const int lane = t & 31;
    const int wid = t >> 5;
    const int n0 = blockIdx.x * 128;
    const int dBase = blockIdx.y * 128;

    const int m_warp = (wid >> 2) * 64;   // 0 or 64
    const int n_warp = (wid & 3) * 32;    // 0..96

    const uint32_t baseA = smem_u32(sA);
    const uint32_t baseB = smem_u32(sB);

    // ---- cp.async destinations (swizzled) ----
    const int a_row = t >> 1;             // 0..127
    const int a_half = t & 1;             // 0/1
    const size_t a_g = (size_t)(dBase + a_row) * CC + a_half * 8;
    const uint32_t a_off = (uint32_t)(a_row * 32 + ((a_half ^ ((a_row >> 2) & 1)) << 4));

    const int b_row = t >> 4;             // 0..15 (k)
    const int b_seg = t & 15;             // 16B chunk (8 n)
    const int n_t = n0 + b_seg * 8;       // 8 | 3136 -> single batch per seg
    const int b_bt = n_t / HWSZ;
    const size_t b_g = ((size_t)b_bt * CC + b_row) * HWSZ + (n_t - b_bt * HWSZ);
    const uint32_t b_off = (uint32_t)(b_row * 256 + ((b_seg ^ (b_row & 7)) << 4));

    // ---- LDSM source offsets (swizzled, stage-invariant) ----
    uint32_t aA_off[4];
    #pragma unroll
    for (int mf = 0; mf < 4; mf++) {
        const int row = m_warp + mf * 16 + (lane & 7) + ((lane >> 3) & 1) * 8;
        const int half = lane >> 4;
        aA_off[mf] = (uint32_t)(row * 32 + ((half ^ ((row >> 2) & 1)) << 4));
    }
    const int b_krow = ((lane >> 3) & 1) * 8 + (lane & 7);
    uint32_t aB_off[2];
    #pragma unroll
    for (int nfp = 0; nfp < 2; nfp++) {
        const int chunk = (n_warp >> 3) + (lane >> 4) + nfp * 2;
        aB_off[nfp] = (uint32_t)(b_krow * 256 + ((chunk ^ (b_krow & 7)) << 4));
    }

    float acc[4][4][4];
    #pragma unroll
    for (int i = 0; i < 4; i++)
        #pragma unroll
        for (int j = 0; j < 4; j++)
            #pragma unroll
            for (int q = 0; q < 4; q++) acc[i][j][q] = 0.f;

    auto load_chunk = [&](int ch, int buf) {
        const int c0 = ch * 16;
        const uint32_t sa = baseA + (uint32_t)buf * A_STAGE_BYTES;
        const uint32_t sb = baseB + (uint32_t)buf * B_STAGE_BYTES;
        cpa16(sa + a_off, g_wb_hi + a_g + c0);
        cpa16(sa + A_MAT_BYTES + a_off, g_wb_lo + a_g + c0);
        cpa16(sb + b_off, g_sc + b_g + (size_t)c0 * HWSZ);
        CPA_COMMIT();
    };

    load_chunk(0, 0);
    load_chunk(1, 1);

    int buf = 0;
    for (int ch = 0; ch < 16; ch++) {
        CPA_WAIT1();
        __syncthreads();

        const uint32_t sa = baseA + (uint32_t)buf * A_STAGE_BYTES;
        const uint32_t sb = baseB + (uint32_t)buf * B_STAGE_BYTES;

        uint32_t bh[4][2];
        #pragma unroll
        for (int nfp = 0; nfp < 2; nfp++) {
            uint32_t r[4];
            ldsm4t(r, sb + aB_off[nfp]);
            bh[nfp * 2 + 0][0] = r[0]; bh[nfp * 2 + 0][1] = r[1];
            bh[nfp * 2 + 1][0] = r[2]; bh[nfp * 2 + 1][1] = r[3];
        }
        #pragma unroll
        for (int mf = 0; mf < 4; mf++) {
            uint32_t ah[4], al[4];
            ldsm4(ah, sa + aA_off[mf]);
            ldsm4(al, sa + A_MAT_BYTES + aA_off[mf]);
            #pragma unroll
            for (int nf = 0; nf < 4; nf++) {
                hmma(acc[mf][nf], ah, bh[nf]);
                hmma(acc[mf][nf], al, bh[nf]);
            }
        }

        const int nxt = ch + 2;
        if (nxt < 16) {
            int nbuf = buf - 1;
            if (nbuf < 0) nbuf = 2;      // (ch+2)%3 given buf=(ch)%3
            load_chunk(nxt, nbuf);
        } else {
            CPA_COMMIT();                 // keep group counting consistent
        }
        buf++;
        if (buf == 3) buf = 0;
    }

    // ---- epilogue (bias via __ldg) ----
    const int g = lane >> 2;
    const int tig = lane & 3;
    #pragma unroll
    for (int mf = 0; mf < 4; mf++) {
        const int d0 = dBase + m_warp + mf * 16 + g;
        const float bb0 = __ldg(bias + d0);
        const float bb1 = __ldg(bias + d0 + 8);
        #pragma unroll
        for (int nf = 0; nf < 4; nf++) {
            const int nt = n0 + n_warp + nf * 8 + tig * 2;
            const int bt = nt / HWSZ;
            const int pp = nt - bt * HWSZ;
            float2 v0, v1;
            v0.x = acc[mf][nf][0] + bb0;
            v0.y = acc[mf][nf][1] + bb0;
            v1.x = acc[mf][nf][2] + bb1;
            v1.y = acc[mf][nf][3] + bb1;
            stcs2(out + ((size_t)bt * CC + d0) * HWSZ + pp, v0);
            stcs2(out + ((size_t)bt * CC + d0 + 8) * HWSZ + pp, v1);
        }
    }
}

// ---------------------------------------------------------------------------
// launch
// ---------------------------------------------------------------------------
extern "C" void kernel_launch(void* const* d_in, const int* in_sizes, int n_in,
                              void* d_out, int out_size) {
    (void)in_sizes; (void)n_in; (void)out_size;
    const float* s      = (const float*)d_in[0];
    const float* r      = (const float*)d_in[1];
    const float* pw1    = (const float*)d_in[2];
    const float* pb1    = (const float*)d_in[3];
    const float* pw2    = (const float*)d_in[4];
    const float* pb2    = (const float*)d_in[5];
    const float* weight = (const float*)d_in[6];
    const float* bscale = (const float*)d_in[7];
    const float* pww    = (const float*)d_in[8];
    const float* pwb    = (const float*)d_in[9];
    float* out = (float*)d_out;

    pool_kernel<<<BB * CC, 256>>>(r);
    wgen_kernel<<<BB, 256>>>(pw1, pb1, pw2, pb2, weight, bscale);
    wconv_kernel<<<CC * CC / 256, 256>>>(pww);
    dw_kernel<<<BB * CC, 224>>>(s);
    dim3 grid(NTOT / 128, CC / 128, 1);
    pw_mma_kernel<<<grid, 256>>>(pwb, out);
}